// round 15
// baseline (speedup 1.0000x reference)
#include <cuda_runtime.h>
#include <cuda_fp16.h>
#include <mma.h>
#include <math.h>
#include <stdint.h>

using namespace nvcuda;

#define B_DIM 1024
#define D_DIM 256
#define NPAD  100352
#define NSPLIT 37
#define NT1 1568           // NPAD / 64

__device__ __half g_projh[B_DIM * D_DIM];
__device__ float g_bias[NPAD];
__device__ __half g_e16[(size_t)B_DIM * NPAD];   // exp(z - pm_tile), fp16
__device__ float g_L[B_DIM];
__device__ float g_pm[(size_t)NT1 * B_DIM];
__device__ float g_ps[(size_t)NT1 * B_DIM];
__device__ __half g_patf[(size_t)NPAD * D_DIM];
__device__ float g_part[(size_t)NSPLIT * B_DIM * D_DIM];
__device__ unsigned g_cmax[NPAD];
__device__ int g_logdmax;

// fast exp on FMA pipe (rel err ~3e-6)
__device__ __forceinline__ float fexp(float x) {
    float y = fmaxf(x * 1.44269504088896f, -126.0f);
    float k = rintf(y);
    float f = y - k;
    float p = 1.3333558146e-3f;
    p = fmaf(p, f, 9.6181291076e-3f);
    p = fmaf(p, f, 5.5504108664e-2f);
    p = fmaf(p, f, 2.4022650696e-1f);
    p = fmaf(p, f, 6.9314718056e-1f);
    p = fmaf(p, f, 1.0f);
    return p * __int_as_float(((int)k + 127) << 23);
}
__device__ __forceinline__ uint32_t pk2h(float lo, float hi) {
    uint32_t d; asm("cvt.rn.f16x2.f32 %0, %1, %2;" : "=r"(d) : "f"(hi), "f"(lo)); return d;
}
__device__ __forceinline__ uint32_t smem_u32(const void* p) {
    uint32_t a;
    asm("{ .reg .u64 t; cvta.to.shared.u64 t, %1; cvt.u32.u64 %0, t; }" : "=r"(a) : "l"(p));
    return a;
}
#define CP16(dst, src) \
    asm volatile("cp.async.cg.shared.global [%0], [%1], 16;" :: "r"(dst), "l"(src))
#define CP_COMMIT() asm volatile("cp.async.commit_group;" ::: "memory")
#define CP_WAIT0()  asm volatile("cp.async.wait_group 0;" ::: "memory")

// -------------------- prep ----------------------------------------------------
__global__ void proj_kernel(const float* __restrict__ state, const float* __restrict__ W) {
    __shared__ float s[D_DIM];
    int b = blockIdx.x, j = threadIdx.x;
    s[j] = state[b * D_DIM + j];
    __syncthreads();
    const float* wr = W + j * D_DIM;
    float acc = 0.f;
#pragma unroll 16
    for (int d = 0; d < D_DIM; ++d) acc = fmaf(s[d], wr[d], acc);
    g_projh[b * D_DIM + j] = __float2half_rn(acc);
}

// patprep also performs init (zero cmax / logdmax); runs BEFORE bias_kernel.
__global__ void patprep_kernel(const float* __restrict__ pat, int Nn) {
    long i = (long)blockIdx.x * 256 + threadIdx.x;
    if (i < Nn) g_cmax[i] = 0u;
    if (i == 0) g_logdmax = 0;
    long e0 = i * 4;
    long n = e0 >> 8;
    float4 v = (n < Nn) ? *(const float4*)&pat[e0] : make_float4(0.f, 0.f, 0.f, 0.f);
    *(uint2*)&g_patf[e0] = make_uint2(pk2h(v.x, v.y), pk2h(v.z, v.w));
}

__global__ void bias_kernel(const float* __restrict__ depths,
                            const float* __restrict__ gate, int Nn) {
    int i = blockIdx.x * 256 + threadIdx.x;
    float lv = 0.f;
    if (i < Nn) {
        float d = depths[i], g = gate[i];
        g_bias[i] = logf(fmaxf(d, 1e-8f)) + logf(fmaxf(g, 1e-8f));
        lv = log1pf(d);
    }
    __shared__ float red[256];
    red[threadIdx.x] = lv;
    __syncthreads();
#pragma unroll
    for (int o = 128; o > 0; o >>= 1) {
        if (threadIdx.x < o) red[threadIdx.x] = fmaxf(red[threadIdx.x], red[threadIdx.x + o]);
        __syncthreads();
    }
    if (threadIdx.x == 0) atomicMax(&g_logdmax, __float_as_int(red[0]));
}

// -------------------- gemm1: e16 = exp(z - pm_tile), z = proj@pat^T + bias ----
// CTA tile 128(M) x 64(N), 8 warps (4x2 of 32x32), k-chunk 64, double buffer.
// smem/stage: A[128][72]h 18432 + B[64][72]h 9216 = 27648; x2 = 55296
// epilogue overlay: float Cs[128][72] = 36864 -> 3 CTAs/SM (acc = 32 regs)
#define SM1_BYTES 55296
#define G1_STAGE 27648
__global__ __launch_bounds__(256, 3) void gemm1_kernel(int Nn) {
    extern __shared__ char sm[];
    const uint32_t sb = smem_u32(sm);
    float* Cs = (float*)sm;
    const int tid = threadIdx.x, wid = tid >> 5;
    const int wm = wid >> 1, wn = wid & 1;              // 4 x 2 warps, tile 32 x 32
    const int m0 = blockIdx.x * 128;
    const long n0 = (long)blockIdx.y * 64;

    wmma::fragment<wmma::accumulator, 16, 16, 16, float> acc[2][2];
#pragma unroll
    for (int mi = 0; mi < 2; ++mi)
#pragma unroll
        for (int ni = 0; ni < 2; ++ni) wmma::fill_fragment(acc[mi][ni], 0.0f);

    const int ar = tid >> 1, ac = (tid & 1) * 32;       // A: 64B per thread
    const int br = tid >> 2, bc = (tid & 3) * 16;       // B: 32B per thread
    const char* sA = (const char*)(g_projh + (size_t)(m0 + ar) * D_DIM + ac);
    const char* sB = (const char*)(g_patf + (n0 + br) * D_DIM + bc);
    const uint32_t dA = sb + ar * 144 + ac * 2;
    const uint32_t dB = sb + 18432 + br * 144 + bc * 2;

#define G1_ISSUE(c, buf) do { \
        long ob = (long)(c) * 128; \
        uint32_t da = dA + (buf) * G1_STAGE, db = dB + (buf) * G1_STAGE; \
        CP16(da, sA + ob); CP16(da + 16, sA + ob + 16); \
        CP16(da + 32, sA + ob + 32); CP16(da + 48, sA + ob + 48); \
        CP16(db, sB + ob); CP16(db + 16, sB + ob + 16); \
        CP_COMMIT(); } while (0)

    G1_ISSUE(0, 0);
    CP_WAIT0();
    __syncthreads();

    for (int c = 0; c < 4; ++c) {
        const int cur = c & 1;
        if (c < 3) G1_ISSUE(c + 1, cur ^ 1);
        const __half* Ah = (const __half*)(sm + cur * G1_STAGE);
        const __half* Bs = (const __half*)(sm + cur * G1_STAGE + 18432);
#pragma unroll
        for (int kk = 0; kk < 64; kk += 16) {
            wmma::fragment<wmma::matrix_a, 16, 16, 16, __half, wmma::row_major> ah[2];
#pragma unroll
            for (int mi = 0; mi < 2; ++mi)
                wmma::load_matrix_sync(ah[mi], &Ah[(wm * 32 + mi * 16) * 72 + kk], 72);
#pragma unroll
            for (int ni = 0; ni < 2; ++ni) {
                wmma::fragment<wmma::matrix_b, 16, 16, 16, __half, wmma::col_major> bh;
                wmma::load_matrix_sync(bh, &Bs[(wn * 32 + ni * 16) * 72 + kk], 72);
                wmma::mma_sync(acc[0][ni], ah[0], bh, acc[0][ni]);
                wmma::mma_sync(acc[1][ni], ah[1], bh, acc[1][ni]);
            }
        }
        if (c < 3) CP_WAIT0();
        __syncthreads();
    }

#pragma unroll
    for (int mi = 0; mi < 2; ++mi)
#pragma unroll
        for (int ni = 0; ni < 2; ++ni)
            wmma::store_matrix_sync(&Cs[(wm * 32 + mi * 16) * 72 + wn * 32 + ni * 16],
                                    acc[mi][ni], 72, wmma::mem_row_major);
    __syncthreads();

    // epilogue: pm = row-tile max of (c + bias); e16 = exp(z - pm); sum; store fp16
    const int r2 = tid >> 1, hc = (tid & 1) * 32;
    const int m = m0 + r2;
    const float* crow = Cs + r2 * 72 + hc;
    float vmax = -3.0e38f;
#pragma unroll
    for (int j = 0; j < 32; j += 4) {
        long n = n0 + hc + j;
        if (n + 4 <= Nn) {
            float4 b4 = *(const float4*)&g_bias[n];
            float4 c4 = *(const float4*)&crow[j];
            vmax = fmaxf(vmax, fmaxf(fmaxf(c4.x + b4.x, c4.y + b4.y),
                                     fmaxf(c4.z + b4.z, c4.w + b4.w)));
        } else {
            for (int q = 0; q < 4; ++q)
                if (n + q < Nn) vmax = fmaxf(vmax, crow[j + q] + g_bias[n + q]);
        }
    }
    float pmv = fmaxf(vmax, __shfl_xor_sync(0xffffffffu, vmax, 1));

    float s = 0.f;
    __half* erow = g_e16 + (size_t)m * NPAD + n0 + hc;
#pragma unroll
    for (int j = 0; j < 32; j += 8) {
        long n = n0 + hc + j;
        uint32_t hh[4];
        if (n + 8 <= Nn) {
            float4 ba = *(const float4*)&g_bias[n];
            float4 ca = *(const float4*)&crow[j];
            float4 bb = *(const float4*)&g_bias[n + 4];
            float4 cb = *(const float4*)&crow[j + 4];
            float e0 = fexp(ca.x + ba.x - pmv), e1 = fexp(ca.y + ba.y - pmv);
            float e2 = fexp(ca.z + ba.z - pmv), e3 = fexp(ca.w + ba.w - pmv);
            float e4 = fexp(cb.x + bb.x - pmv), e5 = fexp(cb.y + bb.y - pmv);
            float e6 = fexp(cb.z + bb.z - pmv), e7 = fexp(cb.w + bb.w - pmv);
            s += (e0 + e1) + (e2 + e3) + (e4 + e5) + (e6 + e7);
            hh[0] = pk2h(e0, e1); hh[1] = pk2h(e2, e3);
            hh[2] = pk2h(e4, e5); hh[3] = pk2h(e6, e7);
        } else {
            float e[8];
            for (int q = 0; q < 8; ++q) {
                long nn = n + q;
                e[q] = (nn < Nn) ? fexp(crow[j + q] + g_bias[nn] - pmv) : 0.f;
                s += e[q];
            }
            hh[0] = pk2h(e[0], e[1]); hh[1] = pk2h(e[2], e[3]);
            hh[2] = pk2h(e[4], e[5]); hh[3] = pk2h(e[6], e[7]);
        }
        *(uint4*)&erow[j] = make_uint4(hh[0], hh[1], hh[2], hh[3]);
    }
    s += __shfl_xor_sync(0xffffffffu, s, 1);
    if ((tid & 1) == 0) {
        g_pm[(size_t)blockIdx.y * B_DIM + m] = pmv;
        g_ps[(size_t)blockIdx.y * B_DIM + m] = s;
    }
}

// -------------------- lse merge -------------------------------------------------
__global__ void lse_merge_kernel(int ntiles) {
    int m = blockIdx.x * 256 + threadIdx.x;
    if (m >= B_DIM) return;
    float M = -3.0e38f;
    for (int t = 0; t < ntiles; ++t) M = fmaxf(M, g_pm[(size_t)t * B_DIM + m]);
    float S = 0.f;
    for (int t = 0; t < ntiles; ++t) {
        float pm = g_pm[(size_t)t * B_DIM + m];
        if (pm > -1.0e38f) S += g_ps[(size_t)t * B_DIM + m] * fexp(pm - M);
    }
    g_L[m] = M + logf(S);
}

// -------------------- gemm2: part = (e16 * s_tile) @ pat + colmax ---------------
// CTA tile 64(M) x 128(D-half), 8 warps (2x4 of 32x32), k-chunk 64, double buffer.
// smem/stage: A[64][72]h 9216 + B[64][136]h 17408 = 26624; x2 = 53248 -> 3 CTAs/SM
// epilogue overlay: float Cs[64][136] = 34816
#define SM2_BYTES 53248
#define G2_STAGE 26624
__global__ __launch_bounds__(256, 3) void gemm2_kernel(int Nn, int CHv) {
    extern __shared__ char sm[];
    const uint32_t sb = smem_u32(sm);
    float* Cs = (float*)sm;
    __shared__ unsigned scm[2][64];
    const int tid = threadIdx.x, wid = tid >> 5, lane = tid & 31;
    const int wm = wid >> 2, wd = wid & 3;              // 2 x 4 warps, tile 32 x 32
    const int mt = blockIdx.x >> 1, dh = blockIdx.x & 1;
    const int m0 = mt * 64, d0 = dh * 128;
    const int sp = blockIdx.y;
    const int ns = sp * CHv, ne = min(ns + CHv, Nn);
    if (ns >= ne) {
        const size_t pb = ((size_t)sp * B_DIM + m0) * D_DIM + d0;
        for (int i = tid; i < 64 * 128 / 4; i += 256) {
            int rr = i >> 5, cc = (i & 31) * 4;
            *(float4*)&g_part[pb + (size_t)rr * D_DIM + cc] = make_float4(0.f, 0.f, 0.f, 0.f);
        }
        return;
    }
    const int nch = (ne - ns + 63) / 64;

    wmma::fragment<wmma::accumulator, 16, 16, 16, float> acc[2][2];
#pragma unroll
    for (int mi = 0; mi < 2; ++mi)
#pragma unroll
        for (int ni = 0; ni < 2; ++ni) wmma::fill_fragment(acc[mi][ni], 0.0f);

    const int r = tid >> 2, ng = (tid & 3) * 16;
    const float Lm = g_L[m0 + r];
    const __half* erow = g_e16 + (size_t)(m0 + r) * NPAD;
    const uint32_t dA = sb + r * 144 + ng * 2;
    if (tid < 64) { scm[0][tid] = 0u; scm[1][tid] = 0u; }
    __syncthreads();

    uint32_t ev[8];   // 16 fp16 e-values

#define G2_ZLOAD(k0v) do { \
        long nbase = (long)(k0v) + ng; \
        *(uint4*)&ev[0] = *(const uint4*)&erow[nbase]; \
        *(uint4*)&ev[4] = *(const uint4*)&erow[nbase + 8]; \
    } while (0)

#define G2_WSTORE(k0v, buf, chpar) do { \
        int t = (int)((k0v) >> 6); \
        float sfac = fexp(g_pm[(size_t)t * B_DIM + m0 + r] - Lm); \
        __half2 sh2 = __float2half2_rn(sfac); \
        __half2 pr[8]; \
        for (int j = 0; j < 8; ++j) \
            pr[j] = __hmul2(*reinterpret_cast<__half2*>(&ev[j]), sh2); \
        uint32_t doff = dA + (buf) * G2_STAGE - sb; \
        *(uint4*)(sm + doff) = *(uint4*)&pr[0]; \
        *(uint4*)(sm + doff + 16) = *(uint4*)&pr[4]; \
        if (dh == 0) { \
            __half2 hm[8]; \
            for (int j = 0; j < 8; ++j) hm[j] = pr[j]; \
            for (int off = 4; off <= 16; off <<= 1) \
                for (int j = 0; j < 8; ++j) { \
                    __half2 o = __shfl_xor_sync(0xffffffffu, hm[j], off); \
                    hm[j] = __hmax2(hm[j], o); \
                } \
            if (lane < 4) \
                for (int j = 0; j < 8; ++j) { \
                    float2 f = __half22float2(hm[j]); \
                    atomicMax(&scm[chpar][lane * 16 + 2 * j], __float_as_uint(f.x)); \
                    atomicMax(&scm[chpar][lane * 16 + 2 * j + 1], __float_as_uint(f.y)); \
                } \
        } \
    } while (0)

#define G2_BISSUE(k0v, buf) do { \
        uint32_t base = sb + (buf) * G2_STAGE + 9216; \
        const char* psrc = (const char*)(g_patf + (size_t)(k0v) * D_DIM + d0); \
        for (int k = 0; k < 4; ++k) { \
            int s0 = tid + k * 256; \
            int rr = s0 >> 4, cc = (s0 & 15) * 16; \
            CP16(base + rr * 272 + cc, psrc + (size_t)rr * 512 + cc); \
        } \
        CP_COMMIT(); } while (0)

    G2_BISSUE(ns, 0);
    G2_ZLOAD(ns);
    G2_WSTORE(ns, 0, 0);
    CP_WAIT0();
    __syncthreads();

    for (int ci = 0; ci < nch; ++ci) {
        const int cur = ci & 1;
        if (dh == 0 && ci > 0 && tid < 64) {
            int n = ns + (ci - 1) * 64 + tid;
            unsigned v = scm[cur ^ 1][tid];
            if (n < Nn && v) atomicMax(&g_cmax[n], v);
            scm[cur ^ 1][tid] = 0u;
        }
        const bool pre = (ci + 1 < nch);
        if (pre) {
            G2_BISSUE(ns + (ci + 1) * 64, cur ^ 1);
            G2_ZLOAD(ns + (ci + 1) * 64);       // prefetch e16 under MMA
        }

        const __half* Ah = (const __half*)(sm + cur * G2_STAGE);
        const __half* Bs = (const __half*)(sm + cur * G2_STAGE + 9216);
#pragma unroll
        for (int kk = 0; kk < 64; kk += 16) {
            wmma::fragment<wmma::matrix_a, 16, 16, 16, __half, wmma::row_major> ah[2];
#pragma unroll
            for (int mi = 0; mi < 2; ++mi)
                wmma::load_matrix_sync(ah[mi], &Ah[(wm * 32 + mi * 16) * 72 + kk], 72);
#pragma unroll
            for (int ni = 0; ni < 2; ++ni) {
                wmma::fragment<wmma::matrix_b, 16, 16, 16, __half, wmma::row_major> bh;
                wmma::load_matrix_sync(bh, &Bs[kk * 136 + wd * 32 + ni * 16], 136);
                wmma::mma_sync(acc[0][ni], ah[0], bh, acc[0][ni]);
                wmma::mma_sync(acc[1][ni], ah[1], bh, acc[1][ni]);
            }
        }
        if (pre) {
            G2_WSTORE(ns + (ci + 1) * 64, cur ^ 1, cur ^ 1);
            CP_WAIT0();
        }
        __syncthreads();
    }
    if (dh == 0 && tid < 64) {
        int n = ns + (nch - 1) * 64 + tid;
        unsigned v = scm[(nch - 1) & 1][tid];
        if (n < Nn && v) atomicMax(&g_cmax[n], v);
    }

#pragma unroll
    for (int mi = 0; mi < 2; ++mi)
#pragma unroll
        for (int ni = 0; ni < 2; ++ni)
            wmma::store_matrix_sync(&Cs[(wm * 32 + mi * 16) * 136 + wd * 32 + ni * 16],
                                    acc[mi][ni], 136, wmma::mem_row_major);
    __syncthreads();
    const int rr = tid >> 2, cgr = (tid & 3) * 32;
    const size_t ob = ((size_t)sp * B_DIM + m0 + rr) * D_DIM + d0 + cgr;
#pragma unroll
    for (int j = 0; j < 32; j += 4)
        *(float4*)&g_part[ob + j] = *(const float4*)&Cs[rr * 136 + cgr + j];
}

// -------------------- reductions / output --------------------------------------
__global__ void reduce_ret_kernel(float* __restrict__ out) {
    size_t i = (size_t)blockIdx.x * 256 + threadIdx.x;
    float4 s = make_float4(0.f, 0.f, 0.f, 0.f);
    for (int sp = 0; sp < NSPLIT; ++sp) {
        float4 v = *(const float4*)&g_part[(size_t)sp * (B_DIM * D_DIM) + i * 4];
        s.x += v.x; s.y += v.y; s.z += v.z; s.w += v.w;
    }
    *(float4*)&out[i * 4] = s;
}

__global__ void depths_kernel(const float* __restrict__ depths,
                              float* __restrict__ out, int Nn) {
    int i = blockIdx.x * 256 + threadIdx.x;
    if (i >= Nn) return;
    float d = depths[i];
    float maxw = __uint_as_float(g_cmax[i]);
    float dom = log1pf(d) / fmaxf(__int_as_float(g_logdmax), 1e-8f);
    float rate = 0.01f * (1.0f - 0.7f * dom);
    out[B_DIM * D_DIM + i] = d + ((maxw > 0.1f) ? rate * maxw : 0.0f);
}

extern "C" void kernel_launch(void* const* d_in, const int* in_sizes, int n_in,
                              void* d_out, int out_size) {
    const float* state  = (const float*)d_in[0];
    const float* W      = (const float*)d_in[1];
    const float* pat    = (const float*)d_in[2];
    const float* depths = (const float*)d_in[3];
    const float* gate   = (const float*)d_in[4];
    float* out = (float*)d_out;
    const int Nn = in_sizes[3];

    cudaFuncSetAttribute(gemm1_kernel, cudaFuncAttributeMaxDynamicSharedMemorySize, SM1_BYTES);
    cudaFuncSetAttribute(gemm2_kernel, cudaFuncAttributeMaxDynamicSharedMemorySize, SM2_BYTES);

    const int nbN = (Nn + 255) / 256;
    proj_kernel<<<B_DIM, 256>>>(state, W);
    patprep_kernel<<<(NPAD * D_DIM / 4) / 256, 256>>>(pat, Nn);   // also does init
    bias_kernel<<<nbN, 256>>>(depths, gate, Nn);

    gemm1_kernel<<<dim3(B_DIM / 128, NT1), 256, SM1_BYTES>>>(Nn);
    lse_merge_kernel<<<B_DIM / 256, 256>>>(NT1);

    const int CHv = ((Nn + NSPLIT * 64 - 1) / (NSPLIT * 64)) * 64;
    gemm2_kernel<<<dim3(2 * (B_DIM / 64), NSPLIT), 256, SM2_BYTES>>>(Nn, CHv);

    reduce_ret_kernel<<<(B_DIM * D_DIM / 4) / 256, 256>>>(out);
    depths_kernel<<<nbN, 256>>>(depths, out, Nn);
}

// round 16
// speedup vs baseline: 1.1151x; 1.1151x over previous
#include <cuda_runtime.h>
#include <cuda_fp16.h>
#include <mma.h>
#include <math.h>
#include <stdint.h>

using namespace nvcuda;

#define B_DIM 1024
#define D_DIM 256
#define NPAD  100352
#define NSPLIT 37
#define NT1 784            // NPAD / 128

__device__ __half g_projh[B_DIM * D_DIM];
__device__ float g_bias[NPAD];
__device__ __half g_e16[(size_t)B_DIM * NPAD];   // exp(z - pm_tile), fp16
__device__ float g_L[B_DIM];
__device__ float g_pm[(size_t)NT1 * B_DIM];
__device__ float g_ps[(size_t)NT1 * B_DIM];
__device__ __half g_patf[(size_t)NPAD * D_DIM];
__device__ float g_part[(size_t)NSPLIT * B_DIM * D_DIM];
__device__ float g_cmaxf[NPAD];
__device__ int g_logdmax;

// fast exp on FMA pipe (rel err ~3e-6) — used only in low-volume reductions
__device__ __forceinline__ float fexp(float x) {
    float y = fmaxf(x * 1.44269504088896f, -126.0f);
    float k = rintf(y);
    float f = y - k;
    float p = 1.3333558146e-3f;
    p = fmaf(p, f, 9.6181291076e-3f);
    p = fmaf(p, f, 5.5504108664e-2f);
    p = fmaf(p, f, 2.4022650696e-1f);
    p = fmaf(p, f, 6.9314718056e-1f);
    p = fmaf(p, f, 1.0f);
    return p * __int_as_float(((int)k + 127) << 23);
}
__device__ __forceinline__ uint32_t pk2h(float lo, float hi) {
    uint32_t d; asm("cvt.rn.f16x2.f32 %0, %1, %2;" : "=r"(d) : "f"(hi), "f"(lo)); return d;
}
__device__ __forceinline__ uint32_t smem_u32(const void* p) {
    uint32_t a;
    asm("{ .reg .u64 t; cvta.to.shared.u64 t, %1; cvt.u32.u64 %0, t; }" : "=r"(a) : "l"(p));
    return a;
}
#define CP16(dst, src) \
    asm volatile("cp.async.cg.shared.global [%0], [%1], 16;" :: "r"(dst), "l"(src))
#define CP_COMMIT() asm volatile("cp.async.commit_group;" ::: "memory")
#define CP_WAIT0()  asm volatile("cp.async.wait_group 0;" ::: "memory")

// -------------------- prep ----------------------------------------------------
__global__ void proj_kernel(const float* __restrict__ state, const float* __restrict__ W) {
    __shared__ float s[D_DIM];
    int b = blockIdx.x, j = threadIdx.x;
    s[j] = state[b * D_DIM + j];
    __syncthreads();
    const float* wr = W + j * D_DIM;
    float acc = 0.f;
#pragma unroll 16
    for (int d = 0; d < D_DIM; ++d) acc = fmaf(s[d], wr[d], acc);
    g_projh[b * D_DIM + j] = __float2half_rn(acc);
}

__global__ void patprep_kernel(const float* __restrict__ pat, int Nn) {
    long i = (long)blockIdx.x * 256 + threadIdx.x;
    if (i == 0) g_logdmax = 0;
    long e0 = i * 4;
    long n = e0 >> 8;
    float4 v = (n < Nn) ? *(const float4*)&pat[e0] : make_float4(0.f, 0.f, 0.f, 0.f);
    *(uint2*)&g_patf[e0] = make_uint2(pk2h(v.x, v.y), pk2h(v.z, v.w));
}

__global__ void bias_kernel(const float* __restrict__ depths,
                            const float* __restrict__ gate, int Nn) {
    int i = blockIdx.x * 256 + threadIdx.x;
    float lv = 0.f;
    if (i < Nn) {
        float d = depths[i], g = gate[i];
        g_bias[i] = logf(fmaxf(d, 1e-8f)) + logf(fmaxf(g, 1e-8f));
        lv = log1pf(d);
    }
    __shared__ float red[256];
    red[threadIdx.x] = lv;
    __syncthreads();
#pragma unroll
    for (int o = 128; o > 0; o >>= 1) {
        if (threadIdx.x < o) red[threadIdx.x] = fmaxf(red[threadIdx.x], red[threadIdx.x + o]);
        __syncthreads();
    }
    if (threadIdx.x == 0) atomicMax(&g_logdmax, __float_as_int(red[0]));
}

// -------------------- gemm1: e16 = exp(z - pm_tile), z = proj@pat^T + bias ----
// CTA tile 128(M) x 128(N), 8 warps (4x2 of 32x64), k-chunks 64, double buffer.
#define SM1_BYTES 73728
#define G1_STAGE 36864
__global__ __launch_bounds__(256, 2) void gemm1_kernel(int Nn) {
    extern __shared__ char sm[];
    const uint32_t sb = smem_u32(sm);
    float* Cs = (float*)sm;
    const int tid = threadIdx.x, wid = tid >> 5;
    const int wm = wid >> 1, wn = wid & 1;              // 4 x 2 warps, tile 32 x 64
    const int m0 = blockIdx.x * 128;
    const long n0 = (long)blockIdx.y * 128;

    wmma::fragment<wmma::accumulator, 16, 16, 16, float> acc[2][4];
#pragma unroll
    for (int mi = 0; mi < 2; ++mi)
#pragma unroll
        for (int ni = 0; ni < 4; ++ni) wmma::fill_fragment(acc[mi][ni], 0.0f);

    const int ar = tid >> 1, ac = (tid & 1) * 32;       // 64B per thread per operand
    const char* sA = (const char*)(g_projh + (size_t)(m0 + ar) * D_DIM + ac);
    const char* sB = (const char*)(g_patf + (n0 + ar) * D_DIM + ac);
    const uint32_t dA = sb + ar * 144 + ac * 2;
    const uint32_t dB = sb + 18432 + ar * 144 + ac * 2;

#define G1_ISSUE(c, buf) do { \
        long ob = (long)(c) * 128; \
        uint32_t da = dA + (buf) * G1_STAGE, db = dB + (buf) * G1_STAGE; \
        CP16(da, sA + ob); CP16(da + 16, sA + ob + 16); \
        CP16(da + 32, sA + ob + 32); CP16(da + 48, sA + ob + 48); \
        CP16(db, sB + ob); CP16(db + 16, sB + ob + 16); \
        CP16(db + 32, sB + ob + 32); CP16(db + 48, sB + ob + 48); \
        CP_COMMIT(); } while (0)

    G1_ISSUE(0, 0);
    CP_WAIT0();
    __syncthreads();

    for (int c = 0; c < 4; ++c) {
        const int cur = c & 1;
        if (c < 3) G1_ISSUE(c + 1, cur ^ 1);
        const __half* Ah = (const __half*)(sm + cur * G1_STAGE);
        const __half* Bs = (const __half*)(sm + cur * G1_STAGE + 18432);
#pragma unroll
        for (int kk = 0; kk < 64; kk += 16) {
            wmma::fragment<wmma::matrix_a, 16, 16, 16, __half, wmma::row_major> ah[2];
#pragma unroll
            for (int mi = 0; mi < 2; ++mi)
                wmma::load_matrix_sync(ah[mi], &Ah[(wm * 32 + mi * 16) * 72 + kk], 72);
#pragma unroll
            for (int ni = 0; ni < 4; ++ni) {
                wmma::fragment<wmma::matrix_b, 16, 16, 16, __half, wmma::col_major> bh;
                wmma::load_matrix_sync(bh, &Bs[(wn * 64 + ni * 16) * 72 + kk], 72);
                wmma::mma_sync(acc[0][ni], ah[0], bh, acc[0][ni]);
                wmma::mma_sync(acc[1][ni], ah[1], bh, acc[1][ni]);
            }
        }
        if (c < 3) CP_WAIT0();
        __syncthreads();
    }

#pragma unroll
    for (int mi = 0; mi < 2; ++mi)
#pragma unroll
        for (int ni = 0; ni < 4; ++ni)
            wmma::store_matrix_sync(&Cs[(wm * 32 + mi * 16) * 136 + wn * 64 + ni * 16],
                                    acc[mi][ni], 136, wmma::mem_row_major);
    __syncthreads();

    // epilogue: pm = row-tile max of (c + bias); e16 = exp(z - pm) via MUFU; sum
    const int r2 = tid >> 1, hc = (tid & 1) * 64;
    const int m = m0 + r2;
    const float* crow = Cs + r2 * 136 + hc;
    float vmax = -3.0e38f;
#pragma unroll
    for (int j = 0; j < 64; j += 4) {
        long n = n0 + hc + j;
        if (n + 4 <= Nn) {
            float4 b4 = *(const float4*)&g_bias[n];
            float4 c4 = *(const float4*)&crow[j];
            vmax = fmaxf(vmax, fmaxf(fmaxf(c4.x + b4.x, c4.y + b4.y),
                                     fmaxf(c4.z + b4.z, c4.w + b4.w)));
        } else {
            for (int q = 0; q < 4; ++q)
                if (n + q < Nn) vmax = fmaxf(vmax, crow[j + q] + g_bias[n + q]);
        }
    }
    float pmv = fmaxf(vmax, __shfl_xor_sync(0xffffffffu, vmax, 1));

    float s = 0.f;
    __half* erow = g_e16 + (size_t)m * NPAD + n0 + hc;
#pragma unroll
    for (int j = 0; j < 64; j += 8) {
        long n = n0 + hc + j;
        uint32_t hh[4];
        if (n + 8 <= Nn) {
            float4 ba = *(const float4*)&g_bias[n];
            float4 ca = *(const float4*)&crow[j];
            float4 bb = *(const float4*)&g_bias[n + 4];
            float4 cb = *(const float4*)&crow[j + 4];
            float e0 = __expf(ca.x + ba.x - pmv), e1 = __expf(ca.y + ba.y - pmv);
            float e2 = __expf(ca.z + ba.z - pmv), e3 = __expf(ca.w + ba.w - pmv);
            float e4 = __expf(cb.x + bb.x - pmv), e5 = __expf(cb.y + bb.y - pmv);
            float e6 = __expf(cb.z + bb.z - pmv), e7 = __expf(cb.w + bb.w - pmv);
            s += (e0 + e1) + (e2 + e3) + (e4 + e5) + (e6 + e7);
            hh[0] = pk2h(e0, e1); hh[1] = pk2h(e2, e3);
            hh[2] = pk2h(e4, e5); hh[3] = pk2h(e6, e7);
        } else {
            float e[8];
            for (int q = 0; q < 8; ++q) {
                long nn = n + q;
                e[q] = (nn < Nn) ? __expf(crow[j + q] + g_bias[nn] - pmv) : 0.f;
                s += e[q];
            }
            hh[0] = pk2h(e[0], e[1]); hh[1] = pk2h(e[2], e[3]);
            hh[2] = pk2h(e[4], e[5]); hh[3] = pk2h(e[6], e[7]);
        }
        *(uint4*)&erow[j] = make_uint4(hh[0], hh[1], hh[2], hh[3]);
    }
    s += __shfl_xor_sync(0xffffffffu, s, 1);
    if ((tid & 1) == 0) {
        g_pm[(size_t)blockIdx.y * B_DIM + m] = pmv;
        g_ps[(size_t)blockIdx.y * B_DIM + m] = s;
    }
}

// -------------------- lse merge -------------------------------------------------
__global__ void lse_merge_kernel(int ntiles) {
    int m = blockIdx.x * 256 + threadIdx.x;
    if (m >= B_DIM) return;
    float M = -3.0e38f;
    for (int t = 0; t < ntiles; ++t) M = fmaxf(M, g_pm[(size_t)t * B_DIM + m]);
    float S = 0.f;
    for (int t = 0; t < ntiles; ++t) {
        float pm = g_pm[(size_t)t * B_DIM + m];
        if (pm > -1.0e38f) S += g_ps[(size_t)t * B_DIM + m] * fexp(pm - M);
    }
    g_L[m] = M + logf(S);
}

// -------------------- colmax: per-column max of w = e16 * sf (streaming) -------
// CTA covers 512 columns (4 pm tiles of 128); sf precomputed per (tile, m).
__global__ __launch_bounds__(256) void colmax_kernel(int Nn) {
    __shared__ __half2 sf2[4][1040];
    const int tid = threadIdx.x;
    const long nb = (long)blockIdx.x * 512;
    const int tbase = (int)(nb >> 7);
    for (int i = tid; i < 4 * B_DIM; i += 256) {
        int tl = i >> 10, m = i & 1023;
        float s = __expf(g_pm[(size_t)(tbase + tl) * B_DIM + m] - g_L[m]);
        sf2[tl][m] = __float2half2_rn(s);
    }
    __syncthreads();
    const long n = nb + tid * 2;
    const int tl = tid >> 6;
    const __half2* ecol = (const __half2*)(g_e16 + n);
    __half2 v0 = __float2half2_rn(0.f), v1 = v0, v2 = v0, v3 = v0;
    for (int m = 0; m < B_DIM; m += 4) {
        __half2 e0 = ecol[(size_t)(m + 0) * (NPAD / 2)];
        __half2 e1 = ecol[(size_t)(m + 1) * (NPAD / 2)];
        __half2 e2 = ecol[(size_t)(m + 2) * (NPAD / 2)];
        __half2 e3 = ecol[(size_t)(m + 3) * (NPAD / 2)];
        v0 = __hmax2(v0, __hmul2(e0, sf2[tl][m + 0]));
        v1 = __hmax2(v1, __hmul2(e1, sf2[tl][m + 1]));
        v2 = __hmax2(v2, __hmul2(e2, sf2[tl][m + 2]));
        v3 = __hmax2(v3, __hmul2(e3, sf2[tl][m + 3]));
    }
    __half2 v = __hmax2(__hmax2(v0, v1), __hmax2(v2, v3));
    float2 f = __half22float2(v);
    if (n < Nn)     g_cmaxf[n] = f.x;
    if (n + 1 < Nn) g_cmaxf[n + 1] = f.y;
}

// -------------------- gemm2: part = (e16 * s_tile) @ pat (colmax removed) ------
#define SM2_BYTES 86016
#define G2_STAGE 43008
__global__ __launch_bounds__(256, 2) void gemm2_kernel(int Nn, int CHv) {
    extern __shared__ char sm[];
    const uint32_t sb = smem_u32(sm);
    float* Cs = (float*)sm;
    const int tid = threadIdx.x, wid = tid >> 5;
    const int wm = wid >> 2, wd = wid & 3;              // 2 x 4 warps, tile 32 x 64
    const int m0 = blockIdx.x * 64;
    const int sp = blockIdx.y;
    const int ns = sp * CHv, ne = min(ns + CHv, Nn);
    if (ns >= ne) {
        const size_t pb = ((size_t)sp * B_DIM + m0) * D_DIM;
        for (int i = tid; i < 64 * D_DIM / 4; i += 256)
            *(float4*)&g_part[pb + (size_t)i * 4] = make_float4(0.f, 0.f, 0.f, 0.f);
        return;
    }
    const int nch = (ne - ns + 63) / 64;

    wmma::fragment<wmma::accumulator, 16, 16, 16, float> acc[2][4];
#pragma unroll
    for (int mi = 0; mi < 2; ++mi)
#pragma unroll
        for (int ni = 0; ni < 4; ++ni) wmma::fill_fragment(acc[mi][ni], 0.0f);

    const int r = tid >> 2, ng = (tid & 3) * 16;
    const float Lm = g_L[m0 + r];
    const __half* erow = g_e16 + (size_t)(m0 + r) * NPAD;
    const uint32_t dA = sb + r * 144 + ng * 2;

    uint32_t ev[8];   // 16 fp16 e-values

#define G2_ZLOAD(k0v) do { \
        long nbase = (long)(k0v) + ng; \
        *(uint4*)&ev[0] = *(const uint4*)&erow[nbase]; \
        *(uint4*)&ev[4] = *(const uint4*)&erow[nbase + 8]; \
    } while (0)

#define G2_WSTORE(k0v, buf) do { \
        int t = (int)((k0v) >> 7); \
        float sfac = __expf(g_pm[(size_t)t * B_DIM + m0 + r] - Lm); \
        __half2 sh2 = __float2half2_rn(sfac); \
        __half2 pr[8]; \
        for (int j = 0; j < 8; ++j) \
            pr[j] = __hmul2(*reinterpret_cast<__half2*>(&ev[j]), sh2); \
        uint32_t doff = dA + (buf) * G2_STAGE - sb; \
        *(uint4*)(sm + doff) = *(uint4*)&pr[0]; \
        *(uint4*)(sm + doff + 16) = *(uint4*)&pr[4]; \
    } while (0)

#define G2_BISSUE(k0v, buf) do { \
        uint32_t base = sb + (buf) * G2_STAGE + 9216; \
        const char* psrc = (const char*)(g_patf + (size_t)(k0v) * D_DIM); \
        for (int k = 0; k < 8; ++k) { \
            int s0 = tid + k * 256; \
            CP16(base + (s0 >> 5) * 528 + (s0 & 31) * 16, psrc + (s0 >> 5) * 512 + (s0 & 31) * 16); \
        } \
        CP_COMMIT(); } while (0)

    G2_BISSUE(ns, 0);
    G2_ZLOAD(ns);
    G2_WSTORE(ns, 0);
    CP_WAIT0();
    __syncthreads();

    for (int ci = 0; ci < nch; ++ci) {
        const int cur = ci & 1;
        const bool pre = (ci + 1 < nch);
        if (pre) {
            G2_BISSUE(ns + (ci + 1) * 64, cur ^ 1);
            G2_ZLOAD(ns + (ci + 1) * 64);       // prefetch e16 under MMA
        }

        const __half* Ah = (const __half*)(sm + cur * G2_STAGE);
        const __half* Bs = (const __half*)(sm + cur * G2_STAGE + 9216);
#pragma unroll
        for (int kk = 0; kk < 64; kk += 16) {
            wmma::fragment<wmma::matrix_a, 16, 16, 16, __half, wmma::row_major> ah[2];
#pragma unroll
            for (int mi = 0; mi < 2; ++mi)
                wmma::load_matrix_sync(ah[mi], &Ah[(wm * 32 + mi * 16) * 72 + kk], 72);
#pragma unroll
            for (int ni = 0; ni < 4; ++ni) {
                wmma::fragment<wmma::matrix_b, 16, 16, 16, __half, wmma::row_major> bh;
                wmma::load_matrix_sync(bh, &Bs[kk * 264 + wd * 64 + ni * 16], 264);
                wmma::mma_sync(acc[0][ni], ah[0], bh, acc[0][ni]);
                wmma::mma_sync(acc[1][ni], ah[1], bh, acc[1][ni]);
            }
        }
        if (pre) {
            G2_WSTORE(ns + (ci + 1) * 64, cur ^ 1);
            CP_WAIT0();
        }
        __syncthreads();
    }

#pragma unroll
    for (int mi = 0; mi < 2; ++mi)
#pragma unroll
        for (int ni = 0; ni < 4; ++ni)
            wmma::store_matrix_sync(&Cs[(wm * 32 + mi * 16) * 264 + wd * 64 + ni * 16],
                                    acc[mi][ni], 264, wmma::mem_row_major);
    __syncthreads();
    const int rr = tid >> 2, cgr = (tid & 3) * 64;
    const size_t ob = ((size_t)sp * B_DIM + m0 + rr) * D_DIM + cgr;
#pragma unroll
    for (int j = 0; j < 64; j += 4)
        *(float4*)&g_part[ob + j] = *(const float4*)&Cs[rr * 264 + cgr + j];
}

// -------------------- reductions / output --------------------------------------
__global__ void reduce_ret_kernel(float* __restrict__ out) {
    size_t i = (size_t)blockIdx.x * 256 + threadIdx.x;
    float4 s = make_float4(0.f, 0.f, 0.f, 0.f);
    for (int sp = 0; sp < NSPLIT; ++sp) {
        float4 v = *(const float4*)&g_part[(size_t)sp * (B_DIM * D_DIM) + i * 4];
        s.x += v.x; s.y += v.y; s.z += v.z; s.w += v.w;
    }
    *(float4*)&out[i * 4] = s;
}

__global__ void depths_kernel(const float* __restrict__ depths,
                              float* __restrict__ out, int Nn) {
    int i = blockIdx.x * 256 + threadIdx.x;
    if (i >= Nn) return;
    float d = depths[i];
    float maxw = g_cmaxf[i];
    float dom = log1pf(d) / fmaxf(__int_as_float(g_logdmax), 1e-8f);
    float rate = 0.01f * (1.0f - 0.7f * dom);
    out[B_DIM * D_DIM + i] = d + ((maxw > 0.1f) ? rate * maxw : 0.0f);
}

extern "C" void kernel_launch(void* const* d_in, const int* in_sizes, int n_in,
                              void* d_out, int out_size) {
    const float* state  = (const float*)d_in[0];
    const float* W      = (const float*)d_in[1];
    const float* pat    = (const float*)d_in[2];
    const float* depths = (const float*)d_in[3];
    const float* gate   = (const float*)d_in[4];
    float* out = (float*)d_out;
    const int Nn = in_sizes[3];

    cudaFuncSetAttribute(gemm1_kernel, cudaFuncAttributeMaxDynamicSharedMemorySize, SM1_BYTES);
    cudaFuncSetAttribute(gemm2_kernel, cudaFuncAttributeMaxDynamicSharedMemorySize, SM2_BYTES);

    const int nbN = (Nn + 255) / 256;
    proj_kernel<<<B_DIM, 256>>>(state, W);
    patprep_kernel<<<(NPAD * D_DIM / 4) / 256, 256>>>(pat, Nn);
    bias_kernel<<<nbN, 256>>>(depths, gate, Nn);

    gemm1_kernel<<<dim3(B_DIM / 128, NT1), 256, SM1_BYTES>>>(Nn);
    lse_merge_kernel<<<B_DIM / 256, 256>>>(NT1);
    colmax_kernel<<<NPAD / 512, 256>>>(Nn);

    const int CHv = ((Nn + NSPLIT * 64 - 1) / (NSPLIT * 64)) * 64;
    gemm2_kernel<<<dim3(B_DIM / 64, NSPLIT), 256, SM2_BYTES>>>(Nn, CHv);

    reduce_ret_kernel<<<(B_DIM * D_DIM / 4) / 256, 256>>>(out);
    depths_kernel<<<nbN, 256>>>(depths, out, Nn);
}

// round 17
// speedup vs baseline: 1.2349x; 1.1075x over previous
#include <cuda_runtime.h>
#include <cuda_fp16.h>
#include <mma.h>
#include <math.h>
#include <stdint.h>

using namespace nvcuda;

#define B_DIM 1024
#define D_DIM 256
#define NPAD  100352
#define NSPLIT 18
#define NT1 784            // NPAD / 128

__device__ __half g_projh[B_DIM * D_DIM];
__device__ float g_bias[NPAD];
__device__ __half g_e16[(size_t)B_DIM * NPAD];   // exp(z - pm_tile), fp16
__device__ float g_L[B_DIM];
__device__ float g_pm[(size_t)NT1 * B_DIM];
__device__ float g_ps[(size_t)NT1 * B_DIM];
__device__ __half g_patf[(size_t)NPAD * D_DIM];
__device__ float g_part[(size_t)NSPLIT * B_DIM * D_DIM];
__device__ unsigned g_cmax[NPAD];
__device__ int g_logdmax;

// fast exp on FMA pipe (rel err ~3e-6) — used only in low-volume reductions
__device__ __forceinline__ float fexp(float x) {
    float y = fmaxf(x * 1.44269504088896f, -126.0f);
    float k = rintf(y);
    float f = y - k;
    float p = 1.3333558146e-3f;
    p = fmaf(p, f, 9.6181291076e-3f);
    p = fmaf(p, f, 5.5504108664e-2f);
    p = fmaf(p, f, 2.4022650696e-1f);
    p = fmaf(p, f, 6.9314718056e-1f);
    p = fmaf(p, f, 1.0f);
    return p * __int_as_float(((int)k + 127) << 23);
}
__device__ __forceinline__ uint32_t pk2h(float lo, float hi) {
    uint32_t d; asm("cvt.rn.f16x2.f32 %0, %1, %2;" : "=r"(d) : "f"(hi), "f"(lo)); return d;
}
__device__ __forceinline__ uint32_t smem_u32(const void* p) {
    uint32_t a;
    asm("{ .reg .u64 t; cvta.to.shared.u64 t, %1; cvt.u32.u64 %0, t; }" : "=r"(a) : "l"(p));
    return a;
}
#define CP16(dst, src) \
    asm volatile("cp.async.cg.shared.global [%0], [%1], 16;" :: "r"(dst), "l"(src))
#define CP_COMMIT() asm volatile("cp.async.commit_group;" ::: "memory")
#define CP_WAIT0()  asm volatile("cp.async.wait_group 0;" ::: "memory")

// -------------------- prep ----------------------------------------------------
__global__ void proj_kernel(const float* __restrict__ state, const float* __restrict__ W) {
    __shared__ float s[D_DIM];
    int b = blockIdx.x, j = threadIdx.x;
    s[j] = state[b * D_DIM + j];
    __syncthreads();
    const float* wr = W + j * D_DIM;
    float acc = 0.f;
#pragma unroll 16
    for (int d = 0; d < D_DIM; ++d) acc = fmaf(s[d], wr[d], acc);
    g_projh[b * D_DIM + j] = __float2half_rn(acc);
}

// patprep also performs init (zero cmax / logdmax); runs BEFORE bias_kernel.
__global__ void patprep_kernel(const float* __restrict__ pat, int Nn) {
    long i = (long)blockIdx.x * 256 + threadIdx.x;
    if (i < Nn) g_cmax[i] = 0u;
    if (i == 0) g_logdmax = 0;
    long e0 = i * 4;
    long n = e0 >> 8;
    float4 v = (n < Nn) ? *(const float4*)&pat[e0] : make_float4(0.f, 0.f, 0.f, 0.f);
    *(uint2*)&g_patf[e0] = make_uint2(pk2h(v.x, v.y), pk2h(v.z, v.w));
}

__global__ void bias_kernel(const float* __restrict__ depths,
                            const float* __restrict__ gate, int Nn) {
    int i = blockIdx.x * 256 + threadIdx.x;
    float lv = 0.f;
    if (i < Nn) {
        float d = depths[i], g = gate[i];
        g_bias[i] = logf(fmaxf(d, 1e-8f)) + logf(fmaxf(g, 1e-8f));
        lv = log1pf(d);
    }
    __shared__ float red[256];
    red[threadIdx.x] = lv;
    __syncthreads();
#pragma unroll
    for (int o = 128; o > 0; o >>= 1) {
        if (threadIdx.x < o) red[threadIdx.x] = fmaxf(red[threadIdx.x], red[threadIdx.x + o]);
        __syncthreads();
    }
    if (threadIdx.x == 0) atomicMax(&g_logdmax, __float_as_int(red[0]));
}

// -------------------- gemm1: e16 = exp(z - pm_tile), z = proj@pat^T + bias ----
// CTA tile 128(M) x 128(N), 8 warps (4x2 of 32x64), k-chunks 64, double buffer.
#define SM1_BYTES 73728
#define G1_STAGE 36864
__global__ __launch_bounds__(256, 2) void gemm1_kernel(int Nn) {
    extern __shared__ char sm[];
    const uint32_t sb = smem_u32(sm);
    float* Cs = (float*)sm;
    const int tid = threadIdx.x, wid = tid >> 5;
    const int wm = wid >> 1, wn = wid & 1;              // 4 x 2 warps, tile 32 x 64
    const int m0 = blockIdx.x * 128;
    const long n0 = (long)blockIdx.y * 128;

    wmma::fragment<wmma::accumulator, 16, 16, 16, float> acc[2][4];
#pragma unroll
    for (int mi = 0; mi < 2; ++mi)
#pragma unroll
        for (int ni = 0; ni < 4; ++ni) wmma::fill_fragment(acc[mi][ni], 0.0f);

    const int ar = tid >> 1, ac = (tid & 1) * 32;       // 64B per thread per operand
    const char* sA = (const char*)(g_projh + (size_t)(m0 + ar) * D_DIM + ac);
    const char* sB = (const char*)(g_patf + (n0 + ar) * D_DIM + ac);
    const uint32_t dA = sb + ar * 144 + ac * 2;
    const uint32_t dB = sb + 18432 + ar * 144 + ac * 2;

#define G1_ISSUE(c, buf) do { \
        long ob = (long)(c) * 128; \
        uint32_t da = dA + (buf) * G1_STAGE, db = dB + (buf) * G1_STAGE; \
        CP16(da, sA + ob); CP16(da + 16, sA + ob + 16); \
        CP16(da + 32, sA + ob + 32); CP16(da + 48, sA + ob + 48); \
        CP16(db, sB + ob); CP16(db + 16, sB + ob + 16); \
        CP16(db + 32, sB + ob + 32); CP16(db + 48, sB + ob + 48); \
        CP_COMMIT(); } while (0)

    G1_ISSUE(0, 0);
    CP_WAIT0();
    __syncthreads();

    for (int c = 0; c < 4; ++c) {
        const int cur = c & 1;
        if (c < 3) G1_ISSUE(c + 1, cur ^ 1);
        const __half* Ah = (const __half*)(sm + cur * G1_STAGE);
        const __half* Bs = (const __half*)(sm + cur * G1_STAGE + 18432);
#pragma unroll
        for (int kk = 0; kk < 64; kk += 16) {
            wmma::fragment<wmma::matrix_a, 16, 16, 16, __half, wmma::row_major> ah[2];
#pragma unroll
            for (int mi = 0; mi < 2; ++mi)
                wmma::load_matrix_sync(ah[mi], &Ah[(wm * 32 + mi * 16) * 72 + kk], 72);
#pragma unroll
            for (int ni = 0; ni < 4; ++ni) {
                wmma::fragment<wmma::matrix_b, 16, 16, 16, __half, wmma::col_major> bh;
                wmma::load_matrix_sync(bh, &Bs[(wn * 64 + ni * 16) * 72 + kk], 72);
                wmma::mma_sync(acc[0][ni], ah[0], bh, acc[0][ni]);
                wmma::mma_sync(acc[1][ni], ah[1], bh, acc[1][ni]);
            }
        }
        if (c < 3) CP_WAIT0();
        __syncthreads();
    }

#pragma unroll
    for (int mi = 0; mi < 2; ++mi)
#pragma unroll
        for (int ni = 0; ni < 4; ++ni)
            wmma::store_matrix_sync(&Cs[(wm * 32 + mi * 16) * 136 + wn * 64 + ni * 16],
                                    acc[mi][ni], 136, wmma::mem_row_major);
    __syncthreads();

    // epilogue: pm = row-tile max of (c + bias); e16 = exp(z - pm) via MUFU; sum
    const int r2 = tid >> 1, hc = (tid & 1) * 64;
    const int m = m0 + r2;
    const float* crow = Cs + r2 * 136 + hc;
    float vmax = -3.0e38f;
#pragma unroll
    for (int j = 0; j < 64; j += 4) {
        long n = n0 + hc + j;
        if (n + 4 <= Nn) {
            float4 b4 = *(const float4*)&g_bias[n];
            float4 c4 = *(const float4*)&crow[j];
            vmax = fmaxf(vmax, fmaxf(fmaxf(c4.x + b4.x, c4.y + b4.y),
                                     fmaxf(c4.z + b4.z, c4.w + b4.w)));
        } else {
            for (int q = 0; q < 4; ++q)
                if (n + q < Nn) vmax = fmaxf(vmax, crow[j + q] + g_bias[n + q]);
        }
    }
    float pmv = fmaxf(vmax, __shfl_xor_sync(0xffffffffu, vmax, 1));

    float s = 0.f;
    __half* erow = g_e16 + (size_t)m * NPAD + n0 + hc;
#pragma unroll
    for (int j = 0; j < 64; j += 8) {
        long n = n0 + hc + j;
        uint32_t hh[4];
        if (n + 8 <= Nn) {
            float4 ba = *(const float4*)&g_bias[n];
            float4 ca = *(const float4*)&crow[j];
            float4 bb = *(const float4*)&g_bias[n + 4];
            float4 cb = *(const float4*)&crow[j + 4];
            float e0 = __expf(ca.x + ba.x - pmv), e1 = __expf(ca.y + ba.y - pmv);
            float e2 = __expf(ca.z + ba.z - pmv), e3 = __expf(ca.w + ba.w - pmv);
            float e4 = __expf(cb.x + bb.x - pmv), e5 = __expf(cb.y + bb.y - pmv);
            float e6 = __expf(cb.z + bb.z - pmv), e7 = __expf(cb.w + bb.w - pmv);
            s += (e0 + e1) + (e2 + e3) + (e4 + e5) + (e6 + e7);
            hh[0] = pk2h(e0, e1); hh[1] = pk2h(e2, e3);
            hh[2] = pk2h(e4, e5); hh[3] = pk2h(e6, e7);
        } else {
            float e[8];
            for (int q = 0; q < 8; ++q) {
                long nn = n + q;
                e[q] = (nn < Nn) ? __expf(crow[j + q] + g_bias[nn] - pmv) : 0.f;
                s += e[q];
            }
            hh[0] = pk2h(e[0], e[1]); hh[1] = pk2h(e[2], e[3]);
            hh[2] = pk2h(e[4], e[5]); hh[3] = pk2h(e[6], e[7]);
        }
        *(uint4*)&erow[j] = make_uint4(hh[0], hh[1], hh[2], hh[3]);
    }
    s += __shfl_xor_sync(0xffffffffu, s, 1);
    if ((tid & 1) == 0) {
        g_pm[(size_t)blockIdx.y * B_DIM + m] = pmv;
        g_ps[(size_t)blockIdx.y * B_DIM + m] = s;
    }
}

// -------------------- lse merge -------------------------------------------------
__global__ void lse_merge_kernel(int ntiles) {
    int m = blockIdx.x * 256 + threadIdx.x;
    if (m >= B_DIM) return;
    float M = -3.0e38f;
    for (int t = 0; t < ntiles; ++t) M = fmaxf(M, g_pm[(size_t)t * B_DIM + m]);
    float S = 0.f;
    for (int t = 0; t < ntiles; ++t) {
        float pm = g_pm[(size_t)t * B_DIM + m];
        if (pm > -1.0e38f) S += g_ps[(size_t)t * B_DIM + m] * fexp(pm - M);
    }
    g_L[m] = M + logf(S);
}

// -------------------- gemm2: part = (e16 * s_tile) @ pat + colmax ---------------
// CTA tile 64(M) x 256(D), 8 warps (2x4 of 32x64), k-chunk 64, double buffer.
#define SM2_BYTES 86016
#define G2_STAGE 43008
__global__ __launch_bounds__(256, 2) void gemm2_kernel(int Nn, int CHv) {
    extern __shared__ char sm[];
    const uint32_t sb = smem_u32(sm);
    float* Cs = (float*)sm;
    __shared__ unsigned scm[2][64];
    const int tid = threadIdx.x, wid = tid >> 5, lane = tid & 31;
    const int wm = wid >> 2, wd = wid & 3;              // 2 x 4 warps, tile 32 x 64
    const int m0 = blockIdx.x * 64;
    const int sp = blockIdx.y;
    const int ns = sp * CHv, ne = min(ns + CHv, Nn);
    if (ns >= ne) {
        const size_t pb = ((size_t)sp * B_DIM + m0) * D_DIM;
        for (int i = tid; i < 64 * D_DIM / 4; i += 256)
            *(float4*)&g_part[pb + (size_t)i * 4] = make_float4(0.f, 0.f, 0.f, 0.f);
        return;
    }
    const int nch = (ne - ns + 63) / 64;

    wmma::fragment<wmma::accumulator, 16, 16, 16, float> acc[2][4];
#pragma unroll
    for (int mi = 0; mi < 2; ++mi)
#pragma unroll
        for (int ni = 0; ni < 4; ++ni) wmma::fill_fragment(acc[mi][ni], 0.0f);

    const int r = tid >> 2, ng = (tid & 3) * 16;
    const float Lm = g_L[m0 + r];
    const __half* erow = g_e16 + (size_t)(m0 + r) * NPAD;
    const uint32_t dA = sb + r * 144 + ng * 2;
    if (tid < 64) { scm[0][tid] = 0u; scm[1][tid] = 0u; }
    __syncthreads();

    uint32_t ev[8];   // 16 fp16 e-values

#define G2_ZLOAD(k0v) do { \
        long nbase = (long)(k0v) + ng; \
        *(uint4*)&ev[0] = *(const uint4*)&erow[nbase]; \
        *(uint4*)&ev[4] = *(const uint4*)&erow[nbase + 8]; \
    } while (0)

#define G2_WSTORE(k0v, buf, chpar) do { \
        int t = (int)((k0v) >> 7); \
        float sfac = __expf(g_pm[(size_t)t * B_DIM + m0 + r] - Lm); \
        __half2 sh2 = __float2half2_rn(sfac); \
        __half2 pr[8]; \
        for (int j = 0; j < 8; ++j) \
            pr[j] = __hmul2(*reinterpret_cast<__half2*>(&ev[j]), sh2); \
        uint32_t doff = dA + (buf) * G2_STAGE - sb; \
        *(uint4*)(sm + doff) = *(uint4*)&pr[0]; \
        *(uint4*)(sm + doff + 16) = *(uint4*)&pr[4]; \
        __half2 hm[8]; \
        for (int j = 0; j < 8; ++j) hm[j] = pr[j]; \
        for (int off = 4; off <= 16; off <<= 1) \
            for (int j = 0; j < 8; ++j) { \
                __half2 o = __shfl_xor_sync(0xffffffffu, hm[j], off); \
                hm[j] = __hmax2(hm[j], o); \
            } \
        if (lane < 4) \
            for (int j = 0; j < 8; ++j) { \
                float2 f = __half22float2(hm[j]); \
                atomicMax(&scm[chpar][lane * 16 + 2 * j], __float_as_uint(f.x)); \
                atomicMax(&scm[chpar][lane * 16 + 2 * j + 1], __float_as_uint(f.y)); \
            } \
    } while (0)

#define G2_BISSUE(k0v, buf) do { \
        uint32_t base = sb + (buf) * G2_STAGE + 9216; \
        const char* psrc = (const char*)(g_patf + (size_t)(k0v) * D_DIM); \
        for (int k = 0; k < 8; ++k) { \
            int s0 = tid + k * 256; \
            CP16(base + (s0 >> 5) * 528 + (s0 & 31) * 16, psrc + (s0 >> 5) * 512 + (s0 & 31) * 16); \
        } \
        CP_COMMIT(); } while (0)

    G2_BISSUE(ns, 0);
    G2_ZLOAD(ns);
    G2_WSTORE(ns, 0, 0);
    CP_WAIT0();
    __syncthreads();

    for (int ci = 0; ci < nch; ++ci) {
        const int cur = ci & 1;
        if (ci > 0 && tid < 64) {
            int n = ns + (ci - 1) * 64 + tid;
            unsigned v = scm[cur ^ 1][tid];
            if (n < Nn && v) atomicMax(&g_cmax[n], v);
            scm[cur ^ 1][tid] = 0u;
        }
        const bool pre = (ci + 1 < nch);
        if (pre) {
            G2_BISSUE(ns + (ci + 1) * 64, cur ^ 1);
            G2_ZLOAD(ns + (ci + 1) * 64);       // prefetch e16 under MMA
        }

        const __half* Ah = (const __half*)(sm + cur * G2_STAGE);
        const __half* Bs = (const __half*)(sm + cur * G2_STAGE + 9216);
#pragma unroll
        for (int kk = 0; kk < 64; kk += 16) {
            wmma::fragment<wmma::matrix_a, 16, 16, 16, __half, wmma::row_major> ah[2];
#pragma unroll
            for (int mi = 0; mi < 2; ++mi)
                wmma::load_matrix_sync(ah[mi], &Ah[(wm * 32 + mi * 16) * 72 + kk], 72);
#pragma unroll
            for (int ni = 0; ni < 4; ++ni) {
                wmma::fragment<wmma::matrix_b, 16, 16, 16, __half, wmma::row_major> bh;
                wmma::load_matrix_sync(bh, &Bs[kk * 264 + wd * 64 + ni * 16], 264);
                wmma::mma_sync(acc[0][ni], ah[0], bh, acc[0][ni]);
                wmma::mma_sync(acc[1][ni], ah[1], bh, acc[1][ni]);
            }
        }
        if (pre) {
            G2_WSTORE(ns + (ci + 1) * 64, cur ^ 1, cur ^ 1);
            CP_WAIT0();
        }
        __syncthreads();
    }
    if (tid < 64) {
        int n = ns + (nch - 1) * 64 + tid;
        unsigned v = scm[(nch - 1) & 1][tid];
        if (n < Nn && v) atomicMax(&g_cmax[n], v);
    }

#pragma unroll
    for (int mi = 0; mi < 2; ++mi)
#pragma unroll
        for (int ni = 0; ni < 4; ++ni)
            wmma::store_matrix_sync(&Cs[(wm * 32 + mi * 16) * 264 + wd * 64 + ni * 16],
                                    acc[mi][ni], 264, wmma::mem_row_major);
    __syncthreads();
    const int rr = tid >> 2, cgr = (tid & 3) * 64;
    const size_t ob = ((size_t)sp * B_DIM + m0 + rr) * D_DIM + cgr;
#pragma unroll
    for (int j = 0; j < 64; j += 4)
        *(float4*)&g_part[ob + j] = *(const float4*)&Cs[rr * 264 + cgr + j];
}

// -------------------- reductions / output --------------------------------------
__global__ void reduce_ret_kernel(float* __restrict__ out) {
    size_t i = (size_t)blockIdx.x * 256 + threadIdx.x;
    float4 s = make_float4(0.f, 0.f, 0.f, 0.f);
    for (int sp = 0; sp < NSPLIT; ++sp) {
        float4 v = *(const float4*)&g_part[(size_t)sp * (B_DIM * D_DIM) + i * 4];
        s.x += v.x; s.y += v.y; s.z += v.z; s.w += v.w;
    }
    *(float4*)&out[i * 4] = s;
}

__global__ void depths_kernel(const float* __restrict__ depths,
                              float* __restrict__ out, int Nn) {
    int i = blockIdx.x * 256 + threadIdx.x;
    if (i >= Nn) return;
    float d = depths[i];
    float maxw = __uint_as_float(g_cmax[i]);
    float dom = log1pf(d) / fmaxf(__int_as_float(g_logdmax), 1e-8f);
    float rate = 0.01f * (1.0f - 0.7f * dom);
    out[B_DIM * D_DIM + i] = d + ((maxw > 0.1f) ? rate * maxw : 0.0f);
}

extern "C" void kernel_launch(void* const* d_in, const int* in_sizes, int n_in,
                              void* d_out, int out_size) {
    const float* state  = (const float*)d_in[0];
    const float* W      = (const float*)d_in[1];
    const float* pat    = (const float*)d_in[2];
    const float* depths = (const float*)d_in[3];
    const float* gate   = (const float*)d_in[4];
    float* out = (float*)d_out;
    const int Nn = in_sizes[3];

    cudaFuncSetAttribute(gemm1_kernel, cudaFuncAttributeMaxDynamicSharedMemorySize, SM1_BYTES);
    cudaFuncSetAttribute(gemm2_kernel, cudaFuncAttributeMaxDynamicSharedMemorySize, SM2_BYTES);

    const int nbN = (Nn + 255) / 256;
    proj_kernel<<<B_DIM, 256>>>(state, W);
    patprep_kernel<<<(NPAD * D_DIM / 4) / 256, 256>>>(pat, Nn);   // also does init
    bias_kernel<<<nbN, 256>>>(depths, gate, Nn);

    gemm1_kernel<<<dim3(B_DIM / 128, NT1), 256, SM1_BYTES>>>(Nn);
    lse_merge_kernel<<<B_DIM / 256, 256>>>(NT1);

    const int CHv = ((Nn + NSPLIT * 64 - 1) / (NSPLIT * 64)) * 64;
    gemm2_kernel<<<dim3(B_DIM / 64, NSPLIT), 256, SM2_BYTES>>>(Nn, CHv);

    reduce_ret_kernel<<<(B_DIM * D_DIM / 4) / 256, 256>>>(out);
    depths_kernel<<<nbN, 256>>>(depths, out, Nn);
}